// round 15
// baseline (speedup 1.0000x reference)
#include <cuda_runtime.h>
#include <cstdint>

// Problem constants (match reference)
#define BOX   120
#define VOL   (BOX * BOX * BOX)       // 1,728,000
#define NTYPE 11
#define BATCH 4
#define BT    (BATCH * NTYPE)         // 44
#define MAXA  512
#define NNB   2

#define THREADS    256
#define YHALF      60                          // y-extent per CTA
#define NROWS      YHALF                       // 60 y-rows per tile
#define ROW_F      BOX                         // 120 floats per row
#define ROW_F4     (BOX / 4)                   // 30 float4 per row
#define ROW_B      (ROW_F * 4)                 // 480 bytes per row
#define PLANE_F    (NROWS * ROW_F)             // 7200 floats
#define PLANE_F4   (PLANE_F / 4)               // 1800 float4
#define NBLOCKS    (BT * BOX * 2)              // 10560 CTAs

// ---------------------------------------------------------------------------
// num_atoms dtype sniff: values in [1,512]. If int64 (LE), 32-bit word 1 is
// the zero high half of element 0; if int32, word 1 is num_atoms[1] >= 1.
// ---------------------------------------------------------------------------
__device__ __forceinline__ int get_natoms(const int* __restrict__ p, int bt) {
    return (p[1] == 0) ? p[2 * bt] : p[bt];
}

__device__ __forceinline__ uint32_t smem_u32(const void* p) {
    uint32_t a;
    asm("{ .reg .u64 t; cvta.to.shared.u64 t, %1; cvt.u32.u64 %0, t; }"
        : "=r"(a) : "l"(p));
    return a;
}

__device__ __forceinline__ void stcs4(float4* addr, float4 v) {
    asm volatile("st.global.cs.v4.f32 [%0], {%1, %2, %3, %4};"
                 :: "l"(addr), "f"(v.x), "f"(v.y), "f"(v.z), "f"(v.w) : "memory");
}

// ---------------------------------------------------------------------------
// Fused kernel (R12 structure + touched-row routing). One CTA of 256 threads
// per (bt, x, y-half). Atom scan marks touched y-rows in a bitmask. Untouched
// rows (~55%) stream zeros straight to gmem, ROW-GRANULAR (full 480B bursts).
// Touched rows are zeroed in smem, scattered into via shared atomics, then
// stored with one cp.async.bulk per contiguous touched-row run (~5 runs).
// Cuts smem STS + TMA smem-read traffic by ~55% vs whole-plane staging.
// ---------------------------------------------------------------------------
__global__ void __launch_bounds__(THREADS) fused_kernel(
    const float* __restrict__ coords,    // [BT, 3*MAXA]
    const int* __restrict__ num_atoms,   // [BT] int32 (or int64, sniffed)
    float* __restrict__ out)             // [BT, VOL]
{
    __shared__ __align__(16) float plane[PLANE_F];   // 28.8 KB
    __shared__ unsigned short alist[MAXA];           // matched atom indices
    __shared__ int acnt;
    __shared__ unsigned rowmask[2];                  // touched-row bits (60)

    const int b  = blockIdx.x;
    const int h  = b & 1;                    // y-half
    const int x  = (b >> 1) % BOX;
    const int bt = b / (BOX * 2);
    const int y0 = h * YHALF;
    const int tid = threadIdx.x;

    const int na = get_natoms(num_atoms, bt);
    const float* cbt = coords + (long long)bt * (3 * MAXA);

    if (tid == 0) { acnt = 0; rowmask[0] = 0u; rowmask[1] = 0u; }
    __syncthreads();

    // Phase 1: scan atoms; collect matches and mark touched y-rows.
    for (int a = tid; a < na; a += THREADS) {
        const float ax = cbt[3 * a + 0];
        const float ay = cbt[3 * a + 1];
        const int cx = (int)floorf(ax);
        const int cy = (int)floorf(ay);
        const int ddx = x - cx;
        if (ddx >= -NNB && ddx <= NNB &&
            cy >= y0 - NNB && cy <= y0 + YHALF - 1 + NNB) {
            alist[atomicAdd(&acnt, 1)] = (unsigned short)a;
            const int rlo = max(cy - NNB - y0, 0);
            const int rhi = min(cy + NNB - y0, NROWS - 1);
            for (int wdi = rlo >> 5; wdi <= (rhi >> 5); wdi++) {
                const int lo = max(rlo - wdi * 32, 0);
                const int hi = min(rhi - wdi * 32, 31);
                const unsigned bits = (hi - lo == 31) ? 0xFFFFFFFFu
                                    : (((1u << (hi - lo + 1)) - 1u) << lo);
                atomicOr(&rowmask[wdi], bits);
            }
        }
    }
    __syncthreads();

    const int cnt = acnt;
    const unsigned m0 = rowmask[0], m1 = rowmask[1];     // one LDS broadcast
    const uint64_t mask64 = (uint64_t)m0 | ((uint64_t)m1 << 32);
    float* dst = out + (long long)bt * VOL + x * (BOX * BOX) + y0 * BOX;
    const float4 zero4 = make_float4(0.f, 0.f, 0.f, 0.f);
    float4* pl4 = (float4*)plane;

    // Phase 2a: untouched rows -> stream zeros straight to gmem, row-granular
    // (one warp stores a full 480B row; partial bursts only at run edges).
    {
        const int wid  = tid >> 5;
        const int lane = tid & 31;
        for (int r = wid; r < NROWS; r += THREADS / 32) {
            if (!((mask64 >> r) & 1ull) && lane < ROW_F4)
                stcs4((float4*)(dst + r * ROW_F) + lane, zero4);
        }
    }

    if (cnt > 0) {
        // Phase 2b: zero touched rows in smem.
        #pragma unroll
        for (int k = 0; k < 8; k++) {
            const int f4 = tid + k * THREADS;
            if (f4 < PLANE_F4) {
                const int r = f4 / ROW_F4;
                if ((mask64 >> r) & 1ull) pl4[f4] = zero4;
            }
        }
        __syncthreads();

        // Phase 3: scatter matched atoms into smem. Warp per atom; lane l<25
        // owns cell (cy + l/5 - 2, cz + l%5 - 2).
        {
            const int wid  = tid >> 5;
            const int lane = tid & 31;
            const float fx = (float)x;
            for (int i = wid; i < cnt; i += THREADS / 32) {
                const int a = alist[i];
                const float ax = cbt[3 * a + 0];
                const float ay = cbt[3 * a + 1];
                const float az = cbt[3 * a + 2];
                if (lane < 25) {
                    const int cy = (int)floorf(ay);
                    const int cz = (int)floorf(az);
                    const int iy = cy + lane / 5 - NNB;
                    const int iz = cz + lane % 5 - NNB;
                    if (iy >= y0 && iy < y0 + YHALF && (unsigned)iz < BOX) {
                        const float dx = fx - ax;
                        const float dy = (float)iy - ay;
                        const float dz = (float)iz - az;
                        const float v = __expf(-(dx * dx + dy * dy + dz * dz));
                        atomicAdd(&plane[(iy - y0) * BOX + iz], v);
                    }
                }
            }
        }
        __syncthreads();

        // Phase 4: one TMA bulk store per contiguous touched-row run.
        if (tid == 0) {
            asm volatile("fence.proxy.async.shared::cta;" ::: "memory");
            const uint32_t srcbase = smem_u32(plane);
            uint64_t m = mask64;
            while (m) {
                const int s = __ffsll((long long)m) - 1;          // run start
                const uint64_t sh = m >> s;
                const int len = __ffsll((long long)(~sh)) - 1;    // run length
                asm volatile("cp.async.bulk.global.shared::cta.bulk_group [%0], [%1], %2;"
                             :: "l"(dst + s * ROW_F),
                                "r"(srcbase + (uint32_t)(s * ROW_B)),
                                "r"((uint32_t)(len * ROW_B)) : "memory");
                m &= ~((((uint64_t)1 << len) - 1) << s);
            }
            asm volatile("cp.async.bulk.commit_group;" ::: "memory");
            asm volatile("cp.async.bulk.wait_group.read 0;" ::: "memory");
        }
    }
}

// ---------------------------------------------------------------------------
extern "C" void kernel_launch(void* const* d_in, const int* in_sizes, int n_in,
                              void* d_out, int out_size) {
    const float* coords    = (const float*)d_in[0];  // float32 [4,11,1536]
    const int*   num_atoms = (const int*)d_in[1];    // int32/int64 [4,11]
    float*       out       = (float*)d_out;          // float32 [4,11,120,120,120]

    fused_kernel<<<NBLOCKS, THREADS>>>(coords, num_atoms, out);
}

// round 16
// speedup vs baseline: 1.0513x; 1.0513x over previous
#include <cuda_runtime.h>
#include <cstdint>

// Problem constants (match reference)
#define BOX   120
#define VOL   (BOX * BOX * BOX)       // 1,728,000
#define NTYPE 11
#define BATCH 4
#define BT    (BATCH * NTYPE)         // 44
#define MAXA  512
#define NNB   2

#define THREADS    256
#define YHALF      60                          // y-extent per CTA
#define PLANE_F    (YHALF * BOX)               // 7200 floats per half-plane
#define PLANE_F4   (PLANE_F / 4)               // 1800 float4 = 7*256 + 8
#define PLANE_B    (PLANE_F * 4)               // 28800 bytes
#define NBLOCKS    (BT * BOX * 2)              // 10560 CTAs

// ---------------------------------------------------------------------------
// num_atoms dtype sniff: values in [1,512]. If int64 (LE), 32-bit word 1 is
// the zero high half of element 0; if int32, word 1 is num_atoms[1] >= 1.
// ---------------------------------------------------------------------------
__device__ __forceinline__ int get_natoms(const int* __restrict__ p, int bt) {
    return (p[1] == 0) ? p[2 * bt] : p[bt];
}

__device__ __forceinline__ uint32_t smem_u32(const void* p) {
    uint32_t a;
    asm("{ .reg .u64 t; cvta.to.shared.u64 t, %1; cvt.u32.u64 %0, t; }"
        : "=r"(a) : "l"(p));
    return a;
}

// ---------------------------------------------------------------------------
// Fused kernel (R12 structure — known best — with issue-side micro-trims).
// One CTA of 256 threads per (bt, x, y-half). Zeroes its 60x120 tile in smem,
// scatters the few matching atoms via shared atomics, then streams the tile
// to gmem with a single cp.async.bulk (perfect 128B bursts, near-zero issue
// cost). Output written exactly once; no global atomics; no pre-zero pass.
// ---------------------------------------------------------------------------
__global__ void __launch_bounds__(THREADS) fused_kernel(
    const float* __restrict__ coords,    // [BT, 3*MAXA]
    const int* __restrict__ num_atoms,   // [BT] int32 (or int64, sniffed)
    float* __restrict__ out)             // [BT, VOL]
{
    __shared__ __align__(16) float plane[PLANE_F];   // 28.8 KB
    __shared__ unsigned short alist[MAXA];           // matched atom indices
    __shared__ int acnt;

    const int b  = blockIdx.x;
    const int h  = b & 1;                    // y-half
    const int x  = (b >> 1) % BOX;
    const int bt = b / (BOX * 2);
    const int y0 = h * YHALF;
    const int tid = threadIdx.x;

    const int na = get_natoms(num_atoms, bt);
    const float* cbt = coords + (long long)bt * (3 * MAXA);

    if (tid == 0) acnt = 0;
    __syncthreads();

    // Phase 1: zero the smem tile AND scan atoms (independent work, one
    // phase; loads and STS interleave for latency hiding).
    float4* pl4 = (float4*)plane;
    const float4 zero4 = make_float4(0.f, 0.f, 0.f, 0.f);
    #pragma unroll
    for (int k = 0; k < 7; k++)
        pl4[tid + k * THREADS] = zero4;             // 7 full strides, no pred
    if (tid < PLANE_F4 - 7 * THREADS)
        pl4[tid + 7 * THREADS] = zero4;             // 8-element tail

    // Fixed 2-unrolled atom scan (MAXA = 2 * THREADS).
    #pragma unroll
    for (int u = 0; u < 2; u++) {
        const int a = tid + u * THREADS;
        if (a < na) {
            const float ax = __ldg(&cbt[3 * a + 0]);
            const float ay = __ldg(&cbt[3 * a + 1]);
            const int cx = (int)floorf(ax);
            const int cy = (int)floorf(ay);
            const int ddx = x - cx;
            if (ddx >= -NNB && ddx <= NNB &&
                cy >= y0 - NNB && cy <= y0 + YHALF - 1 + NNB) {
                alist[atomicAdd(&acnt, 1)] = (unsigned short)a;
            }
        }
    }
    __syncthreads();

    const int cnt = acnt;

    // Phase 2: scatter matched atoms into smem. Warp per atom; lane l < 25
    // owns cell (cy + l/5 - 2, cz + l%5 - 2).
    if (cnt > 0) {
        const int wid  = tid >> 5;
        const int lane = tid & 31;
        const float fx = (float)x;
        for (int i = wid; i < cnt; i += THREADS / 32) {
            const int a = alist[i];
            const float ax = cbt[3 * a + 0];
            const float ay = cbt[3 * a + 1];
            const float az = cbt[3 * a + 2];
            if (lane < 25) {
                const int cy = (int)floorf(ay);
                const int cz = (int)floorf(az);
                const int iy = cy + lane / 5 - NNB;
                const int iz = cz + lane % 5 - NNB;
                if (iy >= y0 && iy < y0 + YHALF && (unsigned)iz < BOX) {
                    const float dx = fx - ax;
                    const float dy = (float)iy - ay;
                    const float dz = (float)iz - az;
                    const float v = __expf(-(dx * dx + dy * dy + dz * dz));
                    atomicAdd(&plane[(iy - y0) * BOX + iz], v);
                }
            }
        }
    }
    __syncthreads();

    // Phase 3: single TMA 1D bulk store smem -> gmem (28.8 KB, 16B-aligned).
    if (tid == 0) {
        float* dst = out + (long long)bt * VOL + x * (BOX * BOX) + y0 * BOX;
        asm volatile("fence.proxy.async.shared::cta;" ::: "memory");
        const uint32_t src = smem_u32(plane);
        asm volatile("cp.async.bulk.global.shared::cta.bulk_group [%0], [%1], %2;"
                     :: "l"(dst), "r"(src), "r"((uint32_t)PLANE_B) : "memory");
        asm volatile("cp.async.bulk.commit_group;" ::: "memory");
        asm volatile("cp.async.bulk.wait_group.read 0;" ::: "memory");
    }
}

// ---------------------------------------------------------------------------
extern "C" void kernel_launch(void* const* d_in, const int* in_sizes, int n_in,
                              void* d_out, int out_size) {
    const float* coords    = (const float*)d_in[0];  // float32 [4,11,1536]
    const int*   num_atoms = (const int*)d_in[1];    // int32/int64 [4,11]
    float*       out       = (float*)d_out;          // float32 [4,11,120,120,120]

    fused_kernel<<<NBLOCKS, THREADS>>>(coords, num_atoms, out);
}

// round 17
// speedup vs baseline: 1.0629x; 1.0111x over previous
#include <cuda_runtime.h>
#include <cstdint>

// Problem constants (match reference)
#define BOX   120
#define VOL   (BOX * BOX * BOX)       // 1,728,000
#define NTYPE 11
#define BATCH 4
#define BT    (BATCH * NTYPE)         // 44
#define MAXA  512
#define NNB   2

#define THREADS    256
#define YHALF      60                          // y-extent per CTA
#define PLANE_F    (YHALF * BOX)               // 7200 floats per half-plane
#define PLANE_F4   (PLANE_F / 4)               // 1800 float4 = 7*256 + 8
#define PLANE_B    (PLANE_F * 4)               // 28800 bytes
#define NBLOCKS    (BT * BOX * 2)              // 10560 CTAs

// ---------------------------------------------------------------------------
// num_atoms dtype sniff: values in [1,512]. If int64 (LE), 32-bit word 1 is
// the zero high half of element 0; if int32, word 1 is num_atoms[1] >= 1.
// ---------------------------------------------------------------------------
__device__ __forceinline__ int get_natoms(const int* __restrict__ p, int bt) {
    return (p[1] == 0) ? p[2 * bt] : p[bt];
}

__device__ __forceinline__ uint32_t smem_u32(const void* p) {
    uint32_t a;
    asm("{ .reg .u64 t; cvta.to.shared.u64 t, %1; cvt.u32.u64 %0, t; }"
        : "=r"(a) : "l"(p));
    return a;
}

// ---------------------------------------------------------------------------
// Fused kernel (converged R12 structure). One CTA of 256 threads per
// (bt, x, y-half). Phase 1 batches ALL scan loads up-front (MLP=4) and hides
// the smem tile zeroing under them; phase 2 scatters matched atoms via shared
// atomics; phase 3 streams the tile to gmem with one cp.async.bulk. Output
// written exactly once; no global atomics; no pre-zero pass.
// ---------------------------------------------------------------------------
__global__ void __launch_bounds__(THREADS) fused_kernel(
    const float* __restrict__ coords,    // [BT, 3*MAXA]
    const int* __restrict__ num_atoms,   // [BT] int32 (or int64, sniffed)
    float* __restrict__ out)             // [BT, VOL]
{
    __shared__ __align__(16) float plane[PLANE_F];   // 28.8 KB
    __shared__ unsigned short alist[MAXA];           // matched atom indices
    __shared__ int acnt;

    const int b  = blockIdx.x;
    const int h  = b & 1;                    // y-half
    const int x  = (b >> 1) % BOX;
    const int bt = b / (BOX * 2);
    const int y0 = h * YHALF;
    const int tid = threadIdx.x;

    const int na = get_natoms(num_atoms, bt);
    const float* cbt = coords + (long long)bt * (3 * MAXA);

    if (tid == 0) acnt = 0;
    __syncthreads();

    // Phase 1: batch ALL scan loads first (MLP=4, one exposed L2 latency),
    // zero the smem tile while they are in flight, then test + append.
    const int a0 = tid;
    const int a1 = tid + THREADS;
    const float ax0 = __ldg(&cbt[3 * a0 + 0]);
    const float ay0 = __ldg(&cbt[3 * a0 + 1]);
    const float ax1 = __ldg(&cbt[3 * a1 + 0]);
    const float ay1 = __ldg(&cbt[3 * a1 + 1]);

    float4* pl4 = (float4*)plane;
    const float4 zero4 = make_float4(0.f, 0.f, 0.f, 0.f);
    #pragma unroll
    for (int k = 0; k < 7; k++)
        pl4[tid + k * THREADS] = zero4;             // 7 full strides, no pred
    if (tid < PLANE_F4 - 7 * THREADS)
        pl4[tid + 7 * THREADS] = zero4;             // 8-element tail

    {
        const int cx0 = (int)floorf(ax0);
        const int cy0 = (int)floorf(ay0);
        const int d0 = x - cx0;
        if (a0 < na && d0 >= -NNB && d0 <= NNB &&
            cy0 >= y0 - NNB && cy0 <= y0 + YHALF - 1 + NNB)
            alist[atomicAdd(&acnt, 1)] = (unsigned short)a0;

        const int cx1 = (int)floorf(ax1);
        const int cy1 = (int)floorf(ay1);
        const int d1 = x - cx1;
        if (a1 < na && d1 >= -NNB && d1 <= NNB &&
            cy1 >= y0 - NNB && cy1 <= y0 + YHALF - 1 + NNB)
            alist[atomicAdd(&acnt, 1)] = (unsigned short)a1;
    }
    __syncthreads();

    const int cnt = acnt;

    // Phase 2: scatter matched atoms into smem. Warp per atom; lane l < 25
    // owns cell (cy + l/5 - 2, cz + l%5 - 2).
    if (cnt > 0) {
        const int wid  = tid >> 5;
        const int lane = tid & 31;
        const float fx = (float)x;
        for (int i = wid; i < cnt; i += THREADS / 32) {
            const int a = alist[i];
            const float ax = cbt[3 * a + 0];
            const float ay = cbt[3 * a + 1];
            const float az = cbt[3 * a + 2];
            if (lane < 25) {
                const int cy = (int)floorf(ay);
                const int cz = (int)floorf(az);
                const int iy = cy + lane / 5 - NNB;
                const int iz = cz + lane % 5 - NNB;
                if (iy >= y0 && iy < y0 + YHALF && (unsigned)iz < BOX) {
                    const float dx = fx - ax;
                    const float dy = (float)iy - ay;
                    const float dz = (float)iz - az;
                    const float v = __expf(-(dx * dx + dy * dy + dz * dz));
                    atomicAdd(&plane[(iy - y0) * BOX + iz], v);
                }
            }
        }
    }
    __syncthreads();

    // Phase 3: single TMA 1D bulk store smem -> gmem (28.8 KB, 16B-aligned).
    if (tid == 0) {
        float* dst = out + (long long)bt * VOL + x * (BOX * BOX) + y0 * BOX;
        asm volatile("fence.proxy.async.shared::cta;" ::: "memory");
        const uint32_t src = smem_u32(plane);
        asm volatile("cp.async.bulk.global.shared::cta.bulk_group [%0], [%1], %2;"
                     :: "l"(dst), "r"(src), "r"((uint32_t)PLANE_B) : "memory");
        asm volatile("cp.async.bulk.commit_group;" ::: "memory");
        asm volatile("cp.async.bulk.wait_group.read 0;" ::: "memory");
    }
}

// ---------------------------------------------------------------------------
extern "C" void kernel_launch(void* const* d_in, const int* in_sizes, int n_in,
                              void* d_out, int out_size) {
    const float* coords    = (const float*)d_in[0];  // float32 [4,11,1536]
    const int*   num_atoms = (const int*)d_in[1];    // int32/int64 [4,11]
    float*       out       = (float*)d_out;          // float32 [4,11,120,120,120]

    fused_kernel<<<NBLOCKS, THREADS>>>(coords, num_atoms, out);
}